// round 2
// baseline (speedup 1.0000x reference)
#include <cuda_runtime.h>
#include <math.h>

#define NUM_CLASSES 10
#define BLOCK 256
#define TILE_ROWS 512                 // floats/tile = 5120 -> 1280 float4 -> 5 per thread
#define GRID_MAIN 1184                // 148 SMs * 8
#define GRID_HIST 256

// log(x) = logf(x * 2^-21) + 21*ln2  (shift folded into finalize)
#define LOG_SCALE (4.76837158203125e-7f)   // 2^-21
#define LOG_SHIFT 21.0

__device__ unsigned int g_counts[16];
__device__ double g_partial_log[GRID_MAIN];
__device__ double g_partial_sq[GRID_MAIN];

__global__ void cse_init_kernel() {
    if (threadIdx.x < 16) g_counts[threadIdx.x] = 0u;
}

// Warp-ballot histogram of target (int32 values in [0,10)) -> g_counts
__global__ void cse_hist_kernel(const int* __restrict__ tgt, int n) {
    const int lane = threadIdx.x & 31;
    const int4* t4 = reinterpret_cast<const int4*>(tgt);
    const int n4 = n >> 2;                        // groups of 4
    const int stride = gridDim.x * blockDim.x;
    const int iters = (n4 + stride - 1) / stride;
    int i = blockIdx.x * blockDim.x + threadIdx.x;

    unsigned int cnt = 0;                          // lane j holds count for class j (j<10)
    for (int it = 0; it < iters; ++it, i += stride) {
        int a = -1, b = -1, cc = -1, d = -1;
        if (i < n4) {
            int4 v = t4[i];
            a = v.x; b = v.y; cc = v.z; d = v.w;
        }
#pragma unroll
        for (int j = 0; j < NUM_CLASSES; j++) {
            unsigned m0 = __ballot_sync(0xffffffffu, a == j);
            unsigned m1 = __ballot_sync(0xffffffffu, b == j);
            unsigned m2 = __ballot_sync(0xffffffffu, cc == j);
            unsigned m3 = __ballot_sync(0xffffffffu, d == j);
            unsigned add = __popc(m0) + __popc(m1) + __popc(m2) + __popc(m3);
            cnt += (lane == j) ? add : 0u;
        }
    }
    // tail (n % 4), n = 2^22 so normally empty
    if (blockIdx.x == 0 && threadIdx.x == 0) {
        for (int r = n4 * 4; r < n; r++) atomicAdd(&g_counts[tgt[r]], 1u);
    }
    if (lane < NUM_CLASSES && cnt) atomicAdd(&g_counts[lane], cnt);
}

// Main fused kernel: ONE pass over outputs.
//  - per row i: dot_i = outputs[i] . counts ; accumulate log(dot_i * 2^-21) via products of 8
//  - accumulate sum of squares of all elements
__global__ void __launch_bounds__(BLOCK, 1)
cse_main_kernel(const float* __restrict__ outp, int n_rows) {
    __shared__ __align__(16) float s_tile[TILE_ROWS * NUM_CLASSES]; // 20480 B
    __shared__ float s_cnt[NUM_CLASSES];
    __shared__ double s_rl[BLOCK / 32];
    __shared__ double s_rq[BLOCK / 32];

    const int tid = threadIdx.x;
    if (tid < NUM_CLASSES) s_cnt[tid] = (float)g_counts[tid];
    __syncthreads();

    float c[NUM_CLASSES];
#pragma unroll
    for (int j = 0; j < NUM_CLASSES; j++) c[j] = s_cnt[j];

    const float4* __restrict__ in4 = reinterpret_cast<const float4*>(outp);
    float4* s4 = reinterpret_cast<float4*>(s_tile);

    const int n_tiles = n_rows / TILE_ROWS;

    double acc_log = 0.0;
    double acc_sq  = 0.0;
    float  prod    = 1.0f;
    int    pcnt    = 0;

    for (int tile = blockIdx.x; tile < n_tiles; tile += GRID_MAIN) {
        size_t base4 = (size_t)tile * (TILE_ROWS * NUM_CLASSES / 4);
#pragma unroll
        for (int k = 0; k < 5; k++) {
            s4[tid + k * BLOCK] = in4[base4 + tid + k * BLOCK];
        }
        __syncthreads();

        // this thread's 2 rows: 20 floats, 16B-aligned (80B per thread)
        const float4* my = reinterpret_cast<const float4*>(s_tile + tid * 2 * NUM_CLASSES);
        float v[20];
#pragma unroll
        for (int k = 0; k < 5; k++) {
            float4 t = my[k];
            v[4 * k + 0] = t.x; v[4 * k + 1] = t.y;
            v[4 * k + 2] = t.z; v[4 * k + 3] = t.w;
        }

        float dot0 = 0.f, dot1 = 0.f, sq = 0.f;
#pragma unroll
        for (int j = 0; j < NUM_CLASSES; j++) {
            dot0 = fmaf(v[j], c[j], dot0);
            dot1 = fmaf(v[NUM_CLASSES + j], c[j], dot1);
        }
#pragma unroll
        for (int k = 0; k < 20; k++) sq = fmaf(v[k], v[k], sq);
        acc_sq += (double)sq;

        prod *= dot0 * LOG_SCALE;
        if (++pcnt == 8) { acc_log += (double)logf(prod); prod = 1.0f; pcnt = 0; }
        prod *= dot1 * LOG_SCALE;
        if (++pcnt == 8) { acc_log += (double)logf(prod); prod = 1.0f; pcnt = 0; }

        __syncthreads();
    }

    // tail rows (n_rows % TILE_ROWS), handled by block 0 directly from gmem
    const int tail_start = n_tiles * TILE_ROWS;
    if (blockIdx.x == 0) {
        for (int r = tail_start + tid; r < n_rows; r += BLOCK) {
            const float* row = outp + (size_t)r * NUM_CLASSES;
            float dot = 0.f, sq = 0.f;
#pragma unroll
            for (int j = 0; j < NUM_CLASSES; j++) {
                float x = row[j];
                dot = fmaf(x, c[j], dot);
                sq  = fmaf(x, x, sq);
            }
            acc_sq  += (double)sq;
            acc_log += (double)logf(dot * LOG_SCALE);
        }
    }

    if (pcnt) acc_log += (double)logf(prod);

    // block reduction (deterministic)
#pragma unroll
    for (int off = 16; off; off >>= 1) {
        acc_log += __shfl_down_sync(0xffffffffu, acc_log, off);
        acc_sq  += __shfl_down_sync(0xffffffffu, acc_sq,  off);
    }
    const int wid = tid >> 5, lane = tid & 31;
    if (lane == 0) { s_rl[wid] = acc_log; s_rq[wid] = acc_sq; }
    __syncthreads();
    if (tid == 0) {
        double a = 0.0, b = 0.0;
#pragma unroll
        for (int w = 0; w < BLOCK / 32; w++) { a += s_rl[w]; b += s_rq[w]; }
        g_partial_log[blockIdx.x] = a;
        g_partial_sq[blockIdx.x]  = b;
    }
}

__global__ void cse_finalize_kernel(float* __restrict__ out, int n_rows) {
    __shared__ double s_l[BLOCK];
    __shared__ double s_q[BLOCK];
    const int tid = threadIdx.x;
    double a = 0.0, b = 0.0;
    for (int i = tid; i < GRID_MAIN; i += BLOCK) {
        a += g_partial_log[i];
        b += g_partial_sq[i];
    }
    s_l[tid] = a; s_q[tid] = b;
    __syncthreads();
    for (int s = BLOCK / 2; s > 0; s >>= 1) {
        if (tid < s) { s_l[tid] += s_l[tid + s]; s_q[tid] += s_q[tid + s]; }
        __syncthreads();
    }
    if (tid == 0) {
        double N = (double)n_rows;
        double sum_log = s_l[0];   // sum of log(dot_i * 2^-21)
        double sum_sq  = s_q[0];
        double mean_log_nom = sum_log / N + LOG_SHIFT * M_LN2;
        double log_denom = 0.5 * log(sum_sq) + 0.5 * log(N); // log(||o||_F * sqrt(N))
        out[0] = (float)(log_denom - mean_log_nom);
    }
}

extern "C" void kernel_launch(void* const* d_in, const int* in_sizes, int n_in,
                              void* d_out, int out_size) {
    // Resolve inputs by size: outputs has NUM_CLASSES x the elements of target.
    int io = 0, it = 1;
    if (n_in >= 2 && in_sizes[1] > in_sizes[0]) { io = 1; it = 0; }
    const float* outputs = (const float*)d_in[io];
    const int*   tgt     = (const int*)d_in[it];      // int32 (JAX x64 disabled downgrades int64)
    const int    n_rows  = in_sizes[it];              // N samples
    float* out           = (float*)d_out;

    cse_init_kernel<<<1, 32>>>();
    cse_hist_kernel<<<GRID_HIST, BLOCK>>>(tgt, n_rows);
    cse_main_kernel<<<GRID_MAIN, BLOCK>>>(outputs, n_rows);
    cse_finalize_kernel<<<1, BLOCK>>>(out, n_rows);
}

// round 3
// speedup vs baseline: 1.1414x; 1.1414x over previous
#include <cuda_runtime.h>
#include <math.h>

#define NUM_CLASSES 10
#define BLOCK 256
#define TILE_ROWS 512                 // floats/tile = 5120 -> 1280 float4 -> 5 per thread
#define GRID_MAIN 592                 // 148 SMs * 4 (register-limited occupancy)
#define GRID_HIST 148

// log(x) = logf(x * 2^-21) + 21*ln2  (shift folded into final math)
#define LOG_SCALE (4.76837158203125e-7f)   // 2^-21
#define LOG_SHIFT 21.0

__device__ float  g_hist_partial[GRID_HIST * NUM_CLASSES];
__device__ double g_partial_log[GRID_MAIN];
__device__ double g_partial_sq[GRID_MAIN];
__device__ unsigned int g_done = 0;   // reset to 0 by last block every run (graph-replay safe)

// ---------------------------------------------------------------------------
// Histogram of target (int32 in [0,10)) -> per-block partial counts (floats).
// Packed counting: 10 classes x 6 bits in one u64, flushed every <=40 elems.
// No global atomics, no init kernel needed.
// ---------------------------------------------------------------------------
__global__ void __launch_bounds__(BLOCK)
cse_hist_kernel(const int* __restrict__ tgt, int n) {
    __shared__ unsigned int s_hist[NUM_CLASSES];
    const int tid = threadIdx.x;
    if (tid < NUM_CLASSES) s_hist[tid] = 0u;
    __syncthreads();

    unsigned int c[NUM_CLASSES];
#pragma unroll
    for (int j = 0; j < NUM_CLASSES; j++) c[j] = 0u;

    const int4* t4 = reinterpret_cast<const int4*>(tgt);
    const int n4 = n >> 2;
    const int stride = gridDim.x * blockDim.x;

    unsigned long long acc = 0ull;
    int since = 0;
    for (int i = blockIdx.x * blockDim.x + tid; i < n4; i += stride) {
        int4 v = __ldcs(&t4[i]);
        acc += 1ull << (6 * v.x);
        acc += 1ull << (6 * v.y);
        acc += 1ull << (6 * v.z);
        acc += 1ull << (6 * v.w);
        if (++since == 10) {              // 40 increments max per 6-bit field
#pragma unroll
            for (int j = 0; j < NUM_CLASSES; j++)
                c[j] += (unsigned int)((acc >> (6 * j)) & 63ull);
            acc = 0ull; since = 0;
        }
    }
    if (since) {
#pragma unroll
        for (int j = 0; j < NUM_CLASSES; j++)
            c[j] += (unsigned int)((acc >> (6 * j)) & 63ull);
    }
    // tail (n % 4) — n = 2^22 so normally empty
    if (blockIdx.x == 0 && tid == 0) {
        for (int r = n4 * 4; r < n; r++) c[tgt[r]]++;
    }

#pragma unroll
    for (int j = 0; j < NUM_CLASSES; j++)
        if (c[j]) atomicAdd(&s_hist[j], c[j]);
    __syncthreads();
    if (tid < NUM_CLASSES)
        g_hist_partial[blockIdx.x * NUM_CLASSES + tid] = (float)s_hist[tid];
}

// ---------------------------------------------------------------------------
// Main fused kernel: ONE pass over outputs + inline final reduction.
//  prologue: sum hist partials -> class counts c[10]
//  loop:     per row i: dot_i = row . c ; log(dot_i*2^-21) via products of 8;
//            sum of squares of all elements
//  epilogue: block partials -> ticket -> last block computes scalar result
// ---------------------------------------------------------------------------
__global__ void __launch_bounds__(BLOCK)
cse_main_kernel(const float* __restrict__ outp, int n_rows, float* __restrict__ out) {
    __shared__ __align__(16) float s_tile[TILE_ROWS * NUM_CLASSES]; // 20480 B
    __shared__ float s_cnt[NUM_CLASSES];
    __shared__ double s_rl[BLOCK / 32];
    __shared__ double s_rq[BLOCK / 32];
    __shared__ bool s_last;

    const int tid = threadIdx.x;

    // --- prologue: reduce hist partials to counts (exact integer floats) ---
    if (tid < NUM_CLASSES) s_cnt[tid] = 0.0f;
    __syncthreads();
    for (int idx = tid; idx < GRID_HIST * NUM_CLASSES; idx += BLOCK)
        atomicAdd(&s_cnt[idx % NUM_CLASSES], g_hist_partial[idx]);
    __syncthreads();

    float c[NUM_CLASSES];
#pragma unroll
    for (int j = 0; j < NUM_CLASSES; j++) c[j] = s_cnt[j];

    const float4* __restrict__ in4 = reinterpret_cast<const float4*>(outp);
    float4* s4 = reinterpret_cast<float4*>(s_tile);

    const int n_tiles = n_rows / TILE_ROWS;

    double acc_log = 0.0;
    double acc_sq  = 0.0;
    float  prod    = 1.0f;
    int    pcnt    = 0;

    for (int tile = blockIdx.x; tile < n_tiles; tile += GRID_MAIN) {
        size_t base4 = (size_t)tile * (TILE_ROWS * NUM_CLASSES / 4);
#pragma unroll
        for (int k = 0; k < 5; k++) {
            s4[tid + k * BLOCK] = __ldcs(&in4[base4 + tid + k * BLOCK]);
        }
        __syncthreads();

        // this thread's 2 rows: 20 floats, 16B-aligned (80B per thread)
        const float4* my = reinterpret_cast<const float4*>(s_tile + tid * 2 * NUM_CLASSES);
        float v[20];
#pragma unroll
        for (int k = 0; k < 5; k++) {
            float4 t = my[k];
            v[4 * k + 0] = t.x; v[4 * k + 1] = t.y;
            v[4 * k + 2] = t.z; v[4 * k + 3] = t.w;
        }

        float dot0 = 0.f, dot1 = 0.f, sq = 0.f;
#pragma unroll
        for (int j = 0; j < NUM_CLASSES; j++) {
            dot0 = fmaf(v[j], c[j], dot0);
            dot1 = fmaf(v[NUM_CLASSES + j], c[j], dot1);
        }
#pragma unroll
        for (int k = 0; k < 20; k++) sq = fmaf(v[k], v[k], sq);
        acc_sq += (double)sq;

        prod *= dot0 * LOG_SCALE;
        if (++pcnt == 8) { acc_log += (double)logf(prod); prod = 1.0f; pcnt = 0; }
        prod *= dot1 * LOG_SCALE;
        if (++pcnt == 8) { acc_log += (double)logf(prod); prod = 1.0f; pcnt = 0; }

        __syncthreads();
    }

    // tail rows (n_rows % TILE_ROWS), handled by block 0 directly from gmem
    const int tail_start = n_tiles * TILE_ROWS;
    if (blockIdx.x == 0) {
        for (int r = tail_start + tid; r < n_rows; r += BLOCK) {
            const float* row = outp + (size_t)r * NUM_CLASSES;
            float dot = 0.f, sq = 0.f;
#pragma unroll
            for (int j = 0; j < NUM_CLASSES; j++) {
                float x = row[j];
                dot = fmaf(x, c[j], dot);
                sq  = fmaf(x, x, sq);
            }
            acc_sq  += (double)sq;
            acc_log += (double)logf(dot * LOG_SCALE);
        }
    }

    if (pcnt) acc_log += (double)logf(prod);

    // --- block reduction (deterministic order) ---
#pragma unroll
    for (int off = 16; off; off >>= 1) {
        acc_log += __shfl_down_sync(0xffffffffu, acc_log, off);
        acc_sq  += __shfl_down_sync(0xffffffffu, acc_sq,  off);
    }
    const int wid = tid >> 5, lane = tid & 31;
    if (lane == 0) { s_rl[wid] = acc_log; s_rq[wid] = acc_sq; }
    __syncthreads();
    if (tid == 0) {
        double a = 0.0, b = 0.0;
#pragma unroll
        for (int w = 0; w < BLOCK / 32; w++) { a += s_rl[w]; b += s_rq[w]; }
        g_partial_log[blockIdx.x] = a;
        g_partial_sq[blockIdx.x]  = b;
        __threadfence();
        unsigned int t = atomicAdd(&g_done, 1u);
        s_last = (t == (unsigned int)(gridDim.x - 1));
    }
    __syncthreads();

    // --- last block: final reduction + scalar math (replaces finalize kernel) ---
    if (s_last) {
        __threadfence();
        double a = 0.0, b = 0.0;
        for (int i = tid; i < GRID_MAIN; i += BLOCK) {
            a += g_partial_log[i];
            b += g_partial_sq[i];
        }
#pragma unroll
        for (int off = 16; off; off >>= 1) {
            a += __shfl_down_sync(0xffffffffu, a, off);
            b += __shfl_down_sync(0xffffffffu, b, off);
        }
        if (lane == 0) { s_rl[wid] = a; s_rq[wid] = b; }
        __syncthreads();
        if (tid == 0) {
            double sa = 0.0, sb = 0.0;
#pragma unroll
            for (int w = 0; w < BLOCK / 32; w++) { sa += s_rl[w]; sb += s_rq[w]; }
            double N = (double)n_rows;
            double mean_log_nom = sa / N + LOG_SHIFT * M_LN2;
            double log_denom = 0.5 * log(sb) + 0.5 * log(N);   // log(||o||_F * sqrt(N))
            out[0] = (float)(log_denom - mean_log_nom);
            g_done = 0;   // reset for next graph replay (deterministic)
        }
    }
}

extern "C" void kernel_launch(void* const* d_in, const int* in_sizes, int n_in,
                              void* d_out, int out_size) {
    // Resolve inputs by size: outputs has NUM_CLASSES x the elements of target.
    int io = 0, it = 1;
    if (n_in >= 2 && in_sizes[1] > in_sizes[0]) { io = 1; it = 0; }
    const float* outputs = (const float*)d_in[io];
    const int*   tgt     = (const int*)d_in[it];      // int32
    const int    n_rows  = in_sizes[it];              // N samples
    float* out           = (float*)d_out;

    cse_hist_kernel<<<GRID_HIST, BLOCK>>>(tgt, n_rows);
    cse_main_kernel<<<GRID_MAIN, BLOCK>>>(outputs, n_rows, out);
}